// round 4
// baseline (speedup 1.0000x reference)
#include <cuda_runtime.h>
#include <cuda_bf16.h>

// Reference output is identically zero (the reference's pad/slice selects the
// zero-pad slice of a size-1 dim and discards all data — verified symbolically
// in R1, rel_err=0 in R2/R3). Fastest correct kernel = zero fill of 411 MB.
//
// R3 measured: DRAM=80.1%, 6.35 TB/s, issue=9.3% — DRAM-write-bound. This
// revision goes persistent (1184 CTAs, grid-stride over tiles) to remove
// wave-transition stalls and keep the store pipe continuously full.

__global__ void __launch_bounds__(256) zero_fill_persist(float4* __restrict__ out,
                                                         long long n4) {
    const float4 z = make_float4(0.f, 0.f, 0.f, 0.f);
    // One tile = 1024 float4s (16 KB), written as 4 warp-coalesced 512B bursts
    // per warp. Persistent CTAs stride over all tiles.
    const long long tiles = (n4 + 1023) >> 10;
    for (long long t = blockIdx.x; t < tiles; t += gridDim.x) {
        long long base = (t << 10) + threadIdx.x;
#pragma unroll
        for (int j = 0; j < 4; j++) {
            long long idx = base + (long long)j * 256;
            if (idx < n4) out[idx] = z;
        }
    }
}

// Scalar tail for out_size % 4 != 0 (dead for this shape; kept for generality).
__global__ void zero_fill_tail(float* __restrict__ out,
                               long long start, long long n_total) {
    long long i = start + (long long)blockIdx.x * blockDim.x + threadIdx.x;
    if (i < n_total) out[i] = 0.f;
}

extern "C" void kernel_launch(void* const* d_in, const int* in_sizes, int n_in,
                              void* d_out, int out_size) {
    (void)d_in; (void)in_sizes; (void)n_in;

    long long n_total = (long long)out_size;   // 102,760,448 expected
    long long n4 = n_total / 4;                // 25,690,112 float4s

    // 148 SMs x 8 resident CTAs (256 thr, 16 regs -> 8 CTAs/SM fits easily).
    const int threads = 256;
    int blocks = 148 * 8;                      // 1184 persistent CTAs
    long long tiles = (n4 + 1023) >> 10;
    if ((long long)blocks > tiles) blocks = (int)(tiles > 0 ? tiles : 1);

    zero_fill_persist<<<blocks, threads>>>((float4*)d_out, n4);

    long long tail = n_total - n4 * 4;         // 0 for this shape
    if (tail > 0) {
        zero_fill_tail<<<1, 256>>>((float*)d_out, n4 * 4, n_total);
    }
}

// round 6
// speedup vs baseline: 1.1653x; 1.1653x over previous
#include <cuda_runtime.h>
#include <cuda_bf16.h>

// Reference output is identically zero (pad/slice of a size-1 dim discards all
// data — verified symbolically R1, rel_err=0 R2-R4). Kernel = 411 MB zero fill.
//
// R4 lesson: persistent CTAs REGRESSED (66.8us, DRAM 66%) — many fire-and-exit
// CTAs maximize outstanding-store parallelism. R5 hit an infra failure
// (device busy at harness init, before any kernel ran) — resubmitting the
// same R3-shaped kernel + dead-predicate removal + streaming store hint.

__device__ __forceinline__ void stcs_f4(float4* p) {
    const float4 z = make_float4(0.f, 0.f, 0.f, 0.f);
    __stcs(p, z);   // st.global.cs.v4 — evict-first, no reuse expected
}

// Fast path: n4 exactly divisible by 1024 (true for this problem:
// 25,690,112 = 1024 * 25,088). No predicates, no tail.
__global__ void __launch_bounds__(256) zero_fill_exact(float4* __restrict__ out) {
    float4* p = out + (long long)blockIdx.x * 1024 + threadIdx.x;
#pragma unroll
    for (int j = 0; j < 4; j++) {
        stcs_f4(p + j * 256);
    }
}

// Generic guarded path (any size) — only used if the shape ever changes.
__global__ void __launch_bounds__(256) zero_fill_guarded(float4* __restrict__ out,
                                                         long long n4) {
    long long base = (long long)blockIdx.x * 1024 + threadIdx.x;
#pragma unroll
    for (int j = 0; j < 4; j++) {
        long long idx = base + (long long)j * 256;
        if (idx < n4) stcs_f4(out + idx);
    }
}

__global__ void zero_fill_tail(float* __restrict__ out,
                               long long start, long long n_total) {
    long long i = start + (long long)blockIdx.x * blockDim.x + threadIdx.x;
    if (i < n_total) out[i] = 0.f;
}

extern "C" void kernel_launch(void* const* d_in, const int* in_sizes, int n_in,
                              void* d_out, int out_size) {
    (void)d_in; (void)in_sizes; (void)n_in;

    long long n_total = (long long)out_size;   // 102,760,448 expected
    long long n4 = n_total / 4;                // 25,690,112 float4s
    const int threads = 256;

    if (n_total % 4096 == 0) {
        // 4096 floats = 1024 float4s per block; exact cover, predicate-free.
        unsigned blocks = (unsigned)(n4 >> 10);        // 25,088
        zero_fill_exact<<<blocks, threads>>>((float4*)d_out);
    } else {
        long long blocks = (n4 + 1023) >> 10;
        if (blocks > 0)
            zero_fill_guarded<<<(unsigned)blocks, threads>>>((float4*)d_out, n4);
        long long tail = n_total - n4 * 4;
        if (tail > 0)
            zero_fill_tail<<<1, 256>>>((float*)d_out, n4 * 4, n_total);
    }
}